// round 5
// baseline (speedup 1.0000x reference)
#include <cuda_runtime.h>
#include <math.h>

#define QTOT 256      // B*P = 4*64
#define DDIM 768
#define NK   2048
#define RR   12
#define KSEL 16
#define SPLITK 4

// static device scratch (no allocations allowed)
__device__ float g_scores[QTOT * NK];                 // 2 MB
__device__ float g_adjsum[(size_t)NK * NK];           // 16 MB
__device__ float g_invnorm[NK];
__device__ float g_nei[QTOT * NK];                    // 2 MB
__device__ float g_part[SPLITK * QTOT * DDIM];        // 3 MB

// ---------------------------------------------------------------------------
// Kernel 1 (fused, single wave = 1184 blocks):
//   blocks [0,128)    : scores GEMM, 64q x 64n tiles, invnorm applied inline
//   blocks [128,160)  : invnorm[n] for later use by the gather kernel
//   blocks [160,1184) : adj_sum[n',n] = sum_r adjacency[r,n',n]  (201 MB read)
// ---------------------------------------------------------------------------
__global__ __launch_bounds__(256, 4) void k_fused1(const float* __restrict__ pos,
                                                   const float* __restrict__ keys,
                                                   const float* __restrict__ adj)
{
    const int bid = blockIdx.x;
    const int t   = threadIdx.x;

    if (bid < 128) {
        // ---------------- scores tile: 64 q x 64 n ----------------
        __shared__ float As[16][68];
        __shared__ float Bs[16][68];
        __shared__ float s_np[4][64];
        __shared__ float s_inv[64];

        const int q0 = (bid >> 5) * 64;   // 4 q-tiles
        const int n0 = (bid & 31) * 64;   // 32 n-tiles
        const int m  = t >> 2;            // 0..63
        const int c  = t & 3;             // 0..3
        const int tx = t & 15;
        const int ty = t >> 4;

        float acc[4][4];
        #pragma unroll
        for (int i = 0; i < 4; i++)
            #pragma unroll
            for (int j = 0; j < 4; j++) acc[i][j] = 0.f;

        const float* pa = pos  + (size_t)(q0 + m) * DDIM + c * 4;
        const float* pb = keys + (size_t)(n0 + m) * DDIM + c * 4;

        for (int d0 = 0; d0 < DDIM; d0 += 16) {
            float4 a = *(const float4*)(pa + d0);
            float4 b = *(const float4*)(pb + d0);
            As[c*4+0][m] = a.x; As[c*4+1][m] = a.y; As[c*4+2][m] = a.z; As[c*4+3][m] = a.w;
            Bs[c*4+0][m] = b.x; Bs[c*4+1][m] = b.y; Bs[c*4+2][m] = b.z; Bs[c*4+3][m] = b.w;
            __syncthreads();
            #pragma unroll
            for (int kk = 0; kk < 16; kk++) {
                float4 av = *(const float4*)&As[kk][ty * 4];
                float4 bv = *(const float4*)&Bs[kk][tx * 4];
                float aa[4] = {av.x, av.y, av.z, av.w};
                float bb[4] = {bv.x, bv.y, bv.z, bv.w};
                #pragma unroll
                for (int i = 0; i < 4; i++)
                    #pragma unroll
                    for (int j = 0; j < 4; j++)
                        acc[i][j] = fmaf(aa[i], bb[j], acc[i][j]);
            }
            __syncthreads();
        }

        // per-tile key norms (reads come from L2; keys tile already hot)
        {
            int n   = t & 63;
            int seg = t >> 6;   // 0..3, each covers 192 contiguous d
            const float* kp = keys + (size_t)(n0 + n) * DDIM + seg * 192;
            float s = 0.f;
            for (int d = 0; d < 192; d++) { float v = kp[d]; s = fmaf(v, v, s); }
            s_np[seg][n] = s;
        }
        __syncthreads();
        if (t < 64) {
            float s = s_np[0][t] + s_np[1][t] + s_np[2][t] + s_np[3][t];
            s_inv[t] = rsqrtf(s + 1e-12f);
        }
        __syncthreads();

        #pragma unroll
        for (int i = 0; i < 4; i++) {
            float4 o;
            o.x = acc[i][0] * s_inv[tx*4+0];
            o.y = acc[i][1] * s_inv[tx*4+1];
            o.z = acc[i][2] * s_inv[tx*4+2];
            o.w = acc[i][3] * s_inv[tx*4+3];
            *(float4*)&g_scores[(size_t)(q0 + ty*4 + i) * NK + n0 + tx*4] = o;
        }
    } else if (bid < 160) {
        // ---------------- invnorm: 32 blocks x 64 keys ----------------
        const int gb   = bid - 128;
        const int wid  = t >> 5;
        const int lane = t & 31;
        for (int i = 0; i < 8; i++) {
            int n = gb * 64 + i * 8 + wid;
            const float* kp = keys + (size_t)n * DDIM;
            float s = 0.f;
            for (int d = lane; d < DDIM; d += 32) { float v = kp[d]; s = fmaf(v, v, s); }
            #pragma unroll
            for (int o = 16; o > 0; o >>= 1) s += __shfl_down_sync(0xffffffffu, s, o);
            if (lane == 0) g_invnorm[n] = rsqrtf(s + 1e-12f);
        }
    } else {
        // ---------------- adj_sum reduction over R ----------------
        const int    nb    = gridDim.x - 160;           // 1024 blocks
        const size_t total = (size_t)NK * NK / 4;       // 1048576 float4
        const float4* a4 = (const float4*)adj;
        float4*       o4 = (float4*)g_adjsum;
        for (size_t i = (size_t)(bid - 160) * 256 + t; i < total; i += (size_t)nb * 256) {
            float4 s = a4[i];
            #pragma unroll
            for (int r = 1; r < RR; r++) {
                float4 v = a4[i + (size_t)r * total];
                s.x += v.x; s.y += v.y; s.z += v.z; s.w += v.w;
            }
            o4[i] = s;
        }
    }
}

// ---------------------------------------------------------------------------
// Kernel 2: per-query top-16 + softmax + weighted gather of adj_sum rows,
//           invnorm folded into nei so the final GEMM uses raw keys_param.
// ---------------------------------------------------------------------------
__global__ __launch_bounds__(256) void k_topk_nei()
{
    __shared__ float s_sc[NK];
    __shared__ float s_w[KSEL];
    __shared__ int   s_off[KSEL];
    __shared__ float s_val[KSEL];
    __shared__ float s_rv[8];
    __shared__ int   s_ri[8];

    const int q    = blockIdx.x;
    const int t    = threadIdx.x;
    const int lane = t & 31;
    const int wid  = t >> 5;

    for (int i = t; i < NK; i += 256) s_sc[i] = g_scores[(size_t)q * NK + i];
    __syncthreads();

    for (int k = 0; k < KSEL; k++) {
        float bv = -INFINITY; int bi = 1 << 30;
        for (int i = t; i < NK; i += 256) {
            float v = s_sc[i];
            if (v > bv || (v == bv && i < bi)) { bv = v; bi = i; }
        }
        #pragma unroll
        for (int o = 16; o > 0; o >>= 1) {
            float ov = __shfl_down_sync(0xffffffffu, bv, o);
            int   oi = __shfl_down_sync(0xffffffffu, bi, o);
            if (ov > bv || (ov == bv && oi < bi)) { bv = ov; bi = oi; }
        }
        if (lane == 0) { s_rv[wid] = bv; s_ri[wid] = bi; }
        __syncthreads();
        if (t == 0) {
            float xv = s_rv[0]; int xi = s_ri[0];
            for (int w = 1; w < 8; w++) {
                float ov = s_rv[w]; int oi = s_ri[w];
                if (ov > xv || (ov == xv && oi < xi)) { xv = ov; xi = oi; }
            }
            s_val[k] = xv; s_off[k] = xi * NK;
            s_sc[xi] = -INFINITY;
        }
        __syncthreads();
    }

    if (t == 0) {
        float vmax = s_val[0];          // first extracted is the max
        float e[KSEL]; float sum = 0.f;
        #pragma unroll
        for (int k = 0; k < KSEL; k++) { e[k] = expf(s_val[k] - vmax); sum += e[k]; }
        float inv = 1.f / sum;
        #pragma unroll
        for (int k = 0; k < KSEL; k++) s_w[k] = e[k] * inv;
    }
    __syncthreads();

    float wv[KSEL]; int off[KSEL];
    #pragma unroll
    for (int k = 0; k < KSEL; k++) { wv[k] = s_w[k]; off[k] = s_off[k]; }

    for (int n = t; n < NK; n += 256) {
        float acc = 0.f;
        #pragma unroll
        for (int k = 0; k < KSEL; k++)
            acc = fmaf(wv[k], g_adjsum[(size_t)off[k] + n], acc);
        g_nei[(size_t)q * NK + n] = acc * g_invnorm[n];
    }
}

// ---------------------------------------------------------------------------
// Kernel 3: out = nei[256,2048] @ keys_param[2048,768], fp32, split-K=4
//           (64x64 tiles, 192 blocks to fill the chip)
// ---------------------------------------------------------------------------
__global__ __launch_bounds__(256) void k_outgemm(const float* __restrict__ keys)
{
    __shared__ float As[16][68];
    __shared__ float Bs[16][68];

    const int m0  = blockIdx.x * 64;             // 4 tiles
    const int n0  = blockIdx.y * 64;             // 12 tiles
    const int kb0 = blockIdx.z * (NK / SPLITK);  // 512-wide slab
    const int t   = threadIdx.x;
    const int tx = t & 15, ty = t >> 4;
    const int ma = t >> 2, ca = t & 3;
    const int kr = t >> 4, xb = t & 15;

    float acc[4][4];
    #pragma unroll
    for (int i = 0; i < 4; i++)
        #pragma unroll
        for (int j = 0; j < 4; j++) acc[i][j] = 0.f;

    for (int kb = kb0; kb < kb0 + NK / SPLITK; kb += 16) {
        float4 a = *(const float4*)&g_nei[(size_t)(m0 + ma) * NK + kb + ca * 4];
        As[ca*4+0][ma] = a.x; As[ca*4+1][ma] = a.y; As[ca*4+2][ma] = a.z; As[ca*4+3][ma] = a.w;
        float4 b = *(const float4*)&keys[(size_t)(kb + kr) * DDIM + n0 + xb * 4];
        *(float4*)&Bs[kr][xb * 4] = b;
        __syncthreads();
        #pragma unroll
        for (int kk = 0; kk < 16; kk++) {
            float4 av = *(const float4*)&As[kk][ty * 4];
            float4 bv = *(const float4*)&Bs[kk][tx * 4];
            float aa[4] = {av.x, av.y, av.z, av.w};
            float bb[4] = {bv.x, bv.y, bv.z, bv.w};
            #pragma unroll
            for (int i = 0; i < 4; i++)
                #pragma unroll
                for (int j = 0; j < 4; j++)
                    acc[i][j] = fmaf(aa[i], bb[j], acc[i][j]);
        }
        __syncthreads();
    }

    float* po = g_part + (size_t)blockIdx.z * QTOT * DDIM;
    #pragma unroll
    for (int i = 0; i < 4; i++) {
        float4 o; o.x = acc[i][0]; o.y = acc[i][1]; o.z = acc[i][2]; o.w = acc[i][3];
        *(float4*)&po[(size_t)(m0 + ty*4 + i) * DDIM + n0 + tx * 4] = o;
    }
}

// ---------------------------------------------------------------------------
// Kernel 4: reduce split-K partials into d_out (fully overwrites output)
// ---------------------------------------------------------------------------
__global__ __launch_bounds__(512) void k_reduce(float* __restrict__ out)
{
    const int i = blockIdx.x * 512 + threadIdx.x;   // over 49152 float4
    const float4* p = (const float4*)g_part;
    float4 s = p[i];
    #pragma unroll
    for (int sk = 1; sk < SPLITK; sk++) {
        float4 v = p[i + (size_t)sk * (QTOT * DDIM / 4)];
        s.x += v.x; s.y += v.y; s.z += v.z; s.w += v.w;
    }
    ((float4*)out)[i] = s;
}

extern "C" void kernel_launch(void* const* d_in, const int* in_sizes, int n_in,
                              void* d_out, int out_size)
{
    const float* pos  = (const float*)d_in[0];   // (4,64,768)
    const float* keys = (const float*)d_in[1];   // (2048,768)
    const float* adj  = (const float*)d_in[2];   // (12,2048,2048)
    (void)in_sizes; (void)n_in; (void)out_size;  // k=16 hardcoded

    k_fused1 <<<1184, 256>>>(pos, keys, adj);    // one full wave: 148 SMs * 8 blocks
    k_topk_nei<<<256, 256>>>();
    k_outgemm <<<dim3(4, 12, SPLITK), 256>>>(keys);
    k_reduce  <<<96, 512>>>((float*)d_out);
}

// round 7
// speedup vs baseline: 1.0874x; 1.0874x over previous
#include <cuda_runtime.h>
#include <math.h>

#define QTOT 256      // B*P = 4*64
#define DDIM 768
#define NK   2048
#define RR   12
#define KSEL 16
#define SPLITK 4

// static device scratch (no allocations allowed)
__device__ float g_scores[QTOT * NK];                 // 2 MB
__device__ float g_adjsum[(size_t)NK * NK];           // 16 MB
__device__ float g_invnorm[NK];
__device__ float g_nei[QTOT * NK];                    // 2 MB
__device__ float g_part[SPLITK * QTOT * DDIM];        // 3 MB

// ---- packed f32x2 helpers (Blackwell FFMA2: 2x fp32 FLOPs per fma-pipe issue)
__device__ __forceinline__ unsigned long long pack2(float lo, float hi) {
    unsigned long long r;
    asm("mov.b64 %0, {%1, %2};" : "=l"(r) : "f"(lo), "f"(hi));
    return r;
}
__device__ __forceinline__ void unpack2(unsigned long long v, float& lo, float& hi) {
    asm("mov.b64 {%0, %1}, %2;" : "=f"(lo), "=f"(hi) : "l"(v));
}
__device__ __forceinline__ unsigned long long fma2(unsigned long long a,
                                                   unsigned long long b,
                                                   unsigned long long c) {
    unsigned long long d;
    asm("fma.rn.f32x2 %0, %1, %2, %3;" : "=l"(d) : "l"(a), "l"(b), "l"(c));
    return d;
}

// ---------------------------------------------------------------------------
// Kernel A: adj_sum[n',n] = sum_r adjacency[r,n',n]  (201 MB streaming read)
// ---------------------------------------------------------------------------
__global__ __launch_bounds__(256) void k_adj(const float* __restrict__ adj)
{
    const size_t total = (size_t)NK * NK / 4;       // 1048576 float4
    const float4* a4 = (const float4*)adj;
    float4*       o4 = (float4*)g_adjsum;
    for (size_t i = (size_t)blockIdx.x * 256 + threadIdx.x; i < total;
         i += (size_t)gridDim.x * 256) {
        float4 s = a4[i];
        #pragma unroll
        for (int r = 1; r < RR; r++) {
            float4 v = a4[i + (size_t)r * total];
            s.x += v.x; s.y += v.y; s.z += v.z; s.w += v.w;
        }
        o4[i] = s;
    }
}

// ---------------------------------------------------------------------------
// Kernel B (160 blocks):
//   blocks [0,128)   : scores GEMM 64q x 64n, FFMA2 inner loop, invnorm inline
//   blocks [128,160) : g_invnorm for the gather kernel
// ---------------------------------------------------------------------------
__global__ __launch_bounds__(256) void k_scores(const float* __restrict__ pos,
                                                const float* __restrict__ keys)
{
    const int bid = blockIdx.x;
    const int t   = threadIdx.x;

    if (bid < 128) {
        __shared__ float As[16][68];
        __shared__ float Bs[16][68];
        __shared__ float s_np[4][64];
        __shared__ float s_inv[64];

        const int q0 = (bid >> 5) * 64;   // 4 q-tiles
        const int n0 = (bid & 31) * 64;   // 32 n-tiles
        const int m  = t >> 2;            // 0..63
        const int c  = t & 3;             // 0..3
        const int tx = t & 15;
        const int ty = t >> 4;

        // acc2[i2][j]: packed over row pairs (ty*4+2*i2, ty*4+2*i2+1), col tx*4+j
        unsigned long long acc2[2][4];
        #pragma unroll
        for (int i = 0; i < 2; i++)
            #pragma unroll
            for (int j = 0; j < 4; j++) acc2[i][j] = 0ull;

        const float* pa = pos  + (size_t)(q0 + m) * DDIM + c * 4;
        const float* pb = keys + (size_t)(n0 + m) * DDIM + c * 4;

        for (int d0 = 0; d0 < DDIM; d0 += 16) {
            float4 a = *(const float4*)(pa + d0);
            float4 b = *(const float4*)(pb + d0);
            As[c*4+0][m] = a.x; As[c*4+1][m] = a.y; As[c*4+2][m] = a.z; As[c*4+3][m] = a.w;
            Bs[c*4+0][m] = b.x; Bs[c*4+1][m] = b.y; Bs[c*4+2][m] = b.z; Bs[c*4+3][m] = b.w;
            __syncthreads();
            #pragma unroll
            for (int kk = 0; kk < 16; kk++) {
                unsigned long long a01 = *(const unsigned long long*)&As[kk][ty * 4];
                unsigned long long a23 = *(const unsigned long long*)&As[kk][ty * 4 + 2];
                float4 bv = *(const float4*)&Bs[kk][tx * 4];
                unsigned long long b0 = pack2(bv.x, bv.x);
                unsigned long long b1 = pack2(bv.y, bv.y);
                unsigned long long b2 = pack2(bv.z, bv.z);
                unsigned long long b3 = pack2(bv.w, bv.w);
                acc2[0][0] = fma2(a01, b0, acc2[0][0]);
                acc2[0][1] = fma2(a01, b1, acc2[0][1]);
                acc2[0][2] = fma2(a01, b2, acc2[0][2]);
                acc2[0][3] = fma2(a01, b3, acc2[0][3]);
                acc2[1][0] = fma2(a23, b0, acc2[1][0]);
                acc2[1][1] = fma2(a23, b1, acc2[1][1]);
                acc2[1][2] = fma2(a23, b2, acc2[1][2]);
                acc2[1][3] = fma2(a23, b3, acc2[1][3]);
            }
            __syncthreads();
        }

        // per-tile key norms (keys tile hot in L2)
        {
            int n   = t & 63;
            int seg = t >> 6;
            const float* kp = keys + (size_t)(n0 + n) * DDIM + seg * 192;
            float s = 0.f;
            for (int d = 0; d < 192; d++) { float v = kp[d]; s = fmaf(v, v, s); }
            s_np[seg][n] = s;
        }
        __syncthreads();
        if (t < 64) {
            float s = s_np[0][t] + s_np[1][t] + s_np[2][t] + s_np[3][t];
            s_inv[t] = rsqrtf(s + 1e-12f);
        }
        __syncthreads();

        // unpack: acc2[i2][j] lo -> row ty*4+2*i2, hi -> row ty*4+2*i2+1
        float accr[4][4];
        #pragma unroll
        for (int i2 = 0; i2 < 2; i2++)
            #pragma unroll
            for (int j = 0; j < 4; j++)
                unpack2(acc2[i2][j], accr[2*i2][j], accr[2*i2+1][j]);

        #pragma unroll
        for (int i = 0; i < 4; i++) {
            float4 o;
            o.x = accr[i][0] * s_inv[tx*4+0];
            o.y = accr[i][1] * s_inv[tx*4+1];
            o.z = accr[i][2] * s_inv[tx*4+2];
            o.w = accr[i][3] * s_inv[tx*4+3];
            *(float4*)&g_scores[(size_t)(q0 + ty*4 + i) * NK + n0 + tx*4] = o;
        }
    } else {
        // ---------------- invnorm: 32 blocks x 64 keys ----------------
        const int gb   = bid - 128;
        const int wid  = t >> 5;
        const int lane = t & 31;
        for (int i = 0; i < 8; i++) {
            int n = gb * 64 + i * 8 + wid;
            const float* kp = keys + (size_t)n * DDIM;
            float s = 0.f;
            for (int d = lane; d < DDIM; d += 32) { float v = kp[d]; s = fmaf(v, v, s); }
            #pragma unroll
            for (int o = 16; o > 0; o >>= 1) s += __shfl_down_sync(0xffffffffu, s, o);
            if (lane == 0) g_invnorm[n] = rsqrtf(s + 1e-12f);
        }
    }
}

// ---------------------------------------------------------------------------
// Kernel 2: per-query top-16 + softmax + weighted gather of adj_sum rows,
//           invnorm folded into nei so the final GEMM uses raw keys_param.
// ---------------------------------------------------------------------------
__global__ __launch_bounds__(256) void k_topk_nei()
{
    __shared__ float s_sc[NK];
    __shared__ float s_w[KSEL];
    __shared__ int   s_off[KSEL];
    __shared__ float s_val[KSEL];
    __shared__ float s_rv[8];
    __shared__ int   s_ri[8];

    const int q    = blockIdx.x;
    const int t    = threadIdx.x;
    const int lane = t & 31;
    const int wid  = t >> 5;

    for (int i = t; i < NK; i += 256) s_sc[i] = g_scores[(size_t)q * NK + i];
    __syncthreads();

    for (int k = 0; k < KSEL; k++) {
        float bv = -INFINITY; int bi = 1 << 30;
        for (int i = t; i < NK; i += 256) {
            float v = s_sc[i];
            if (v > bv || (v == bv && i < bi)) { bv = v; bi = i; }
        }
        #pragma unroll
        for (int o = 16; o > 0; o >>= 1) {
            float ov = __shfl_down_sync(0xffffffffu, bv, o);
            int   oi = __shfl_down_sync(0xffffffffu, bi, o);
            if (ov > bv || (ov == bv && oi < bi)) { bv = ov; bi = oi; }
        }
        if (lane == 0) { s_rv[wid] = bv; s_ri[wid] = bi; }
        __syncthreads();
        if (t == 0) {
            float xv = s_rv[0]; int xi = s_ri[0];
            for (int w = 1; w < 8; w++) {
                float ov = s_rv[w]; int oi = s_ri[w];
                if (ov > xv || (ov == xv && oi < xi)) { xv = ov; xi = oi; }
            }
            s_val[k] = xv; s_off[k] = xi * NK;
            s_sc[xi] = -INFINITY;
        }
        __syncthreads();
    }

    if (t == 0) {
        float vmax = s_val[0];          // first extracted is the max
        float e[KSEL]; float sum = 0.f;
        #pragma unroll
        for (int k = 0; k < KSEL; k++) { e[k] = expf(s_val[k] - vmax); sum += e[k]; }
        float inv = 1.f / sum;
        #pragma unroll
        for (int k = 0; k < KSEL; k++) s_w[k] = e[k] * inv;
    }
    __syncthreads();

    float wv[KSEL]; int off[KSEL];
    #pragma unroll
    for (int k = 0; k < KSEL; k++) { wv[k] = s_w[k]; off[k] = s_off[k]; }

    for (int n = t; n < NK; n += 256) {
        float acc = 0.f;
        #pragma unroll
        for (int k = 0; k < KSEL; k++)
            acc = fmaf(wv[k], g_adjsum[(size_t)off[k] + n], acc);
        g_nei[(size_t)q * NK + n] = acc * g_invnorm[n];
    }
}

// ---------------------------------------------------------------------------
// Kernel 3: out = nei[256,2048] @ keys_param[2048,768], fp32 FFMA2, split-K=4
// ---------------------------------------------------------------------------
__global__ __launch_bounds__(256) void k_outgemm(const float* __restrict__ keys)
{
    __shared__ float As[16][68];
    __shared__ float Bs[16][68];

    const int m0  = blockIdx.x * 64;             // 4 tiles
    const int n0  = blockIdx.y * 64;             // 12 tiles
    const int kb0 = blockIdx.z * (NK / SPLITK);  // 512-wide slab
    const int t   = threadIdx.x;
    const int tx = t & 15, ty = t >> 4;
    const int ma = t >> 2, ca = t & 3;
    const int kr = t >> 4, xb = t & 15;

    unsigned long long acc2[2][4];
    #pragma unroll
    for (int i = 0; i < 2; i++)
        #pragma unroll
        for (int j = 0; j < 4; j++) acc2[i][j] = 0ull;

    for (int kb = kb0; kb < kb0 + NK / SPLITK; kb += 16) {
        float4 a = *(const float4*)&g_nei[(size_t)(m0 + ma) * NK + kb + ca * 4];
        As[ca*4+0][ma] = a.x; As[ca*4+1][ma] = a.y; As[ca*4+2][ma] = a.z; As[ca*4+3][ma] = a.w;
        float4 b = *(const float4*)&keys[(size_t)(kb + kr) * DDIM + n0 + xb * 4];
        *(float4*)&Bs[kr][xb * 4] = b;
        __syncthreads();
        #pragma unroll
        for (int kk = 0; kk < 16; kk++) {
            unsigned long long a01 = *(const unsigned long long*)&As[kk][ty * 4];
            unsigned long long a23 = *(const unsigned long long*)&As[kk][ty * 4 + 2];
            float4 bv = *(const float4*)&Bs[kk][tx * 4];
            unsigned long long b0 = pack2(bv.x, bv.x);
            unsigned long long b1 = pack2(bv.y, bv.y);
            unsigned long long b2 = pack2(bv.z, bv.z);
            unsigned long long b3 = pack2(bv.w, bv.w);
            acc2[0][0] = fma2(a01, b0, acc2[0][0]);
            acc2[0][1] = fma2(a01, b1, acc2[0][1]);
            acc2[0][2] = fma2(a01, b2, acc2[0][2]);
            acc2[0][3] = fma2(a01, b3, acc2[0][3]);
            acc2[1][0] = fma2(a23, b0, acc2[1][0]);
            acc2[1][1] = fma2(a23, b1, acc2[1][1]);
            acc2[1][2] = fma2(a23, b2, acc2[1][2]);
            acc2[1][3] = fma2(a23, b3, acc2[1][3]);
        }
        __syncthreads();
    }

    float accr[4][4];
    #pragma unroll
    for (int i2 = 0; i2 < 2; i2++)
        #pragma unroll
        for (int j = 0; j < 4; j++)
            unpack2(acc2[i2][j], accr[2*i2][j], accr[2*i2+1][j]);

    float* po = g_part + (size_t)blockIdx.z * QTOT * DDIM;
    #pragma unroll
    for (int i = 0; i < 4; i++) {
        float4 o; o.x = accr[i][0]; o.y = accr[i][1]; o.z = accr[i][2]; o.w = accr[i][3];
        *(float4*)&po[(size_t)(m0 + ty*4 + i) * DDIM + n0 + tx * 4] = o;
    }
}

// ---------------------------------------------------------------------------
// Kernel 4: reduce split-K partials into d_out (fully overwrites output)
// ---------------------------------------------------------------------------
__global__ __launch_bounds__(512) void k_reduce(float* __restrict__ out)
{
    const int i = blockIdx.x * 512 + threadIdx.x;   // over 49152 float4
    const float4* p = (const float4*)g_part;
    float4 s = p[i];
    #pragma unroll
    for (int sk = 1; sk < SPLITK; sk++) {
        float4 v = p[i + (size_t)sk * (QTOT * DDIM / 4)];
        s.x += v.x; s.y += v.y; s.z += v.z; s.w += v.w;
    }
    ((float4*)out)[i] = s;
}

extern "C" void kernel_launch(void* const* d_in, const int* in_sizes, int n_in,
                              void* d_out, int out_size)
{
    const float* pos  = (const float*)d_in[0];   // (4,64,768)
    const float* keys = (const float*)d_in[1];   // (2048,768)
    const float* adj  = (const float*)d_in[2];   // (12,2048,2048)
    (void)in_sizes; (void)n_in; (void)out_size;  // k=16 hardcoded

    k_adj     <<<1024, 256>>>(adj);
    k_scores  <<<160, 256>>>(pos, keys);
    k_topk_nei<<<256, 256>>>();
    k_outgemm <<<dim3(4, 12, SPLITK), 256>>>(keys);
    k_reduce  <<<96, 512>>>((float*)d_out);
}